// round 16
// baseline (speedup 1.0000x reference)
#include <cuda_runtime.h>
#include <cuda_bf16.h>
#include <cuda_fp16.h>
#include <cstdint>

// Problem constants
#define BB    2
#define NQ    4096
#define NS    8
#define NTOT  4104          // NQ + NS
#define CC    192
#define HH    8
#define DD    24            // CC / HH
#define MROWS (BB*NTOT)     // 8208
#define NKP   4224          // padded to 33*128
#define QTILES 33           // q-tiles of 128
#define KTILES2 33          // k-tiles of 128
#define LOG2E 1.4426950408889634f

// packed row widths (elements)
#define QK_COLS 88          // 80 data cols (5 ksteps x16) + 8 pad; 176B rows
#define V_COLS  40          // fp16: 24 data + ones col @24 + pad; 80B rows
#define PK_COLS 576         // packed B row: 6 chunks x 96

typedef unsigned long long u64;

// ---------------------------------------------------------------------------
// helpers
// ---------------------------------------------------------------------------
__device__ __forceinline__ float ex2f(float x) {
    float r; asm("ex2.approx.f32 %0, %1;" : "=f"(r) : "f"(x)); return r;
}
__device__ __forceinline__ uint32_t cvt_bf2(float hi, float lo) {
    uint32_t r; asm("cvt.rn.bf16x2.f32 %0, %1, %2;" : "=r"(r) : "f"(hi), "f"(lo)); return r;
}
__device__ __forceinline__ uint32_t cvt_f16x2(float hi, float lo) {
    uint32_t r; asm("cvt.rn.f16x2.f32 %0, %1, %2;" : "=r"(r) : "f"(hi), "f"(lo)); return r;
}
__device__ __forceinline__ uint32_t ex2_f16x2(uint32_t x) {
    uint32_t r; asm("ex2.approx.f16x2 %0, %1;" : "=r"(r) : "r"(x)); return r;
}
__device__ __forceinline__ void hmma_bf(float (&c)[4],
                                        uint32_t a0, uint32_t a1, uint32_t a2, uint32_t a3,
                                        uint32_t b0, uint32_t b1) {
    asm volatile(
        "mma.sync.aligned.m16n8k16.row.col.f32.bf16.bf16.f32 "
        "{%0,%1,%2,%3},{%4,%5,%6,%7},{%8,%9},{%0,%1,%2,%3};"
        : "+f"(c[0]), "+f"(c[1]), "+f"(c[2]), "+f"(c[3])
        : "r"(a0), "r"(a1), "r"(a2), "r"(a3), "r"(b0), "r"(b1));
}
__device__ __forceinline__ void hmma_f16(float (&c)[4],
                                         uint32_t a0, uint32_t a1, uint32_t a2, uint32_t a3,
                                         uint32_t b0, uint32_t b1) {
    asm volatile(
        "mma.sync.aligned.m16n8k16.row.col.f32.f16.f16.f32 "
        "{%0,%1,%2,%3},{%4,%5,%6,%7},{%8,%9},{%0,%1,%2,%3};"
        : "+f"(c[0]), "+f"(c[1]), "+f"(c[2]), "+f"(c[3])
        : "r"(a0), "r"(a1), "r"(a2), "r"(a3), "r"(b0), "r"(b1));
}
__device__ __forceinline__ uint32_t smem_u32(const void* p) {
    uint32_t a;
    asm("{ .reg .u64 t; cvta.to.shared.u64 t, %1; cvt.u32.u64 %0, t; }" : "=r"(a) : "l"(p));
    return a;
}
__device__ __forceinline__ void ldsm_x2(uint32_t& r0, uint32_t& r1, uint32_t addr) {
    asm volatile("ldmatrix.sync.aligned.m8n8.x2.shared.b16 {%0,%1}, [%2];"
                 : "=r"(r0), "=r"(r1) : "r"(addr));
}
__device__ __forceinline__ void ldsm_x4(uint32_t& r0, uint32_t& r1, uint32_t& r2, uint32_t& r3,
                                        uint32_t addr) {
    asm volatile("ldmatrix.sync.aligned.m8n8.x4.shared.b16 {%0,%1,%2,%3}, [%4];"
                 : "=r"(r0), "=r"(r1), "=r"(r2), "=r"(r3) : "r"(addr));
}
__device__ __forceinline__ void ldsm_x2_t(uint32_t& r0, uint32_t& r1, uint32_t addr) {
    asm volatile("ldmatrix.sync.aligned.m8n8.x2.trans.shared.b16 {%0,%1}, [%2];"
                 : "=r"(r0), "=r"(r1) : "r"(addr));
}
#define CP16(dst, src) \
    asm volatile("cp.async.cg.shared.global [%0], [%1], 16;" :: "r"(dst), "l"(src))
#define CP_COMMIT() asm volatile("cp.async.commit_group;" ::: "memory")
#define CP_WAIT(n)  asm volatile("cp.async.wait_group %0;" :: "n"(n) : "memory")

// ---------------------------------------------------------------------------
// Scratch (device globals; zero-initialized -> pad rows/cols stay 0)
// ---------------------------------------------------------------------------
__device__ __align__(16) __nv_bfloat16 g_Qp[16*NKP*QK_COLS];
__device__ __align__(16) __nv_bfloat16 g_Kp[16*NKP*QK_COLS];
__device__ __align__(16) __half        g_Vf[16*NKP*V_COLS];
__device__ __align__(16) float g_O[BB*NTOT*CC];
__device__ __align__(16) __nv_bfloat16 g_Bq[576*PK_COLS];
__device__ __align__(16) __nv_bfloat16 g_Bo[192*PK_COLS];

// ---------------------------------------------------------------------------
// 0) Pack B: fp32 weight rows -> packed bf16 chunk rows [bh|bh|bl] (one-time).
// ---------------------------------------------------------------------------
__global__ void pack_b_kernel(const float* __restrict__ W, __nv_bfloat16* __restrict__ dst,
                              int rows) {
    int idx = blockIdx.x * 256 + threadIdx.x;
    if (idx >= rows * 6) return;
    int row = idx / 6, ch = idx % 6;
    const float* src = W + (size_t)row * CC + ch * 32;
    uint32_t h[16], l[16];
    #pragma unroll
    for (int q = 0; q < 8; q++) {
        float4 x = *reinterpret_cast<const float4*>(src + q * 4);
        uint32_t h0 = cvt_bf2(x.y, x.x);
        float r0 = x.x - __uint_as_float(h0 << 16);
        float r1 = x.y - __uint_as_float(h0 & 0xffff0000u);
        uint32_t h1 = cvt_bf2(x.w, x.z);
        float r2 = x.z - __uint_as_float(h1 << 16);
        float r3 = x.w - __uint_as_float(h1 & 0xffff0000u);
        h[q*2]   = h0; l[q*2]   = cvt_bf2(r1, r0);
        h[q*2+1] = h1; l[q*2+1] = cvt_bf2(r3, r2);
    }
    uint4* d = reinterpret_cast<uint4*>(dst + (size_t)row * PK_COLS + ch * 96);
    #pragma unroll
    for (int i = 0; i < 4; i++) d[i]     = make_uint4(h[i*4], h[i*4+1], h[i*4+2], h[i*4+3]);
    #pragma unroll
    for (int i = 0; i < 4; i++) d[4 + i] = make_uint4(h[i*4], h[i*4+1], h[i*4+2], h[i*4+3]);
    #pragma unroll
    for (int i = 0; i < 4; i++) d[8 + i] = make_uint4(l[i*4], l[i*4+1], l[i*4+2], l[i*4+3]);
}

// ---------------------------------------------------------------------------
// 1&3) Split GEMM: A fp32 + in-kernel split, B pre-packed + cp.async (R15).
// ---------------------------------------------------------------------------
#define GSTRIDE 104         // packed row stride in bf16 elems (208 B)

template<int MODE>
__global__ __launch_bounds__(128)
void split_gemm_kernel(const float* __restrict__ X,
                       const float* __restrict__ S,
                       const __nv_bfloat16* __restrict__ Bp,
                       const float* __restrict__ T,
                       float* __restrict__ out) {
    __shared__ __align__(16) __nv_bfloat16 sA[64 * GSTRIDE];
    __shared__ __align__(16) __nv_bfloat16 sB[2][64 * GSTRIDE];

    const int tid = threadIdx.x;
    const int w   = tid >> 5;
    const int t   = tid & 31;
    const int mw  = w >> 1;
    const int nw  = w & 1;
    const int m0  = blockIdx.x * 64;
    const int n0  = blockIdx.y * 64;

    const int srow = tid >> 1;
    const int half = tid & 1;

    const float* Arow = nullptr;
    if (MODE == 0) {
        int gr = m0 + srow;
        if (gr < MROWS) {
            int b = (gr >= NTOT) ? 1 : 0;
            int n = gr - b * NTOT;
            if (n < NQ) Arow = X + (size_t)(b * NQ + n) * CC;
            else        Arow = S + (size_t)(b * NS + (n - NQ)) * CC;
        }
    } else {
        int gr = m0 + srow;
        int b = gr >> 12;
        int n = gr & 4095;
        Arow = g_O + (size_t)(b * NTOT + n) * CC;
    }
    const __nv_bfloat16* Brow = Bp + (size_t)(n0 + srow) * PK_COLS;

    auto stageB = [&](int ch, int buf) {
        const __nv_bfloat16* bs = Brow + ch * 96 + half * 48;
        uint32_t bd = smem_u32(&sB[buf][0]) + srow * 208 + half * 96;
        #pragma unroll
        for (int u = 0; u < 6; u++) CP16(bd + u * 16, bs + u * 8);
    };

    stageB(0, 0);
    CP_COMMIT();

    float av[16];
    const int acb = half;
    {
        #pragma unroll
        for (int q = 0; q < 4; q++) {
            float4 x = Arow ? *reinterpret_cast<const float4*>(Arow + acb * 16 + q * 4)
                            : make_float4(0.f, 0.f, 0.f, 0.f);
            av[q*4+0]=x.x; av[q*4+1]=x.y; av[q*4+2]=x.z; av[q*4+3]=x.w;
        }
    }

    float C[2][4][4];
    #pragma unroll
    for (int mt = 0; mt < 2; mt++)
        #pragma unroll
        for (int nt = 0; nt < 4; nt++)
            #pragma unroll
            for (int c = 0; c < 4; c++) C[mt][nt][c] = 0.f;

    const uint32_t sAb = smem_u32(sA);

    for (int kc = 0; kc < 6; kc++) {
        {
            uint32_t ah[8], al[8];
            #pragma unroll
            for (int i = 0; i < 8; i++) {
                float a0 = av[2*i], a1 = av[2*i+1];
                uint32_t hp = cvt_bf2(a1, a0);
                float r0 = a0 - __uint_as_float(hp << 16);
                float r1 = a1 - __uint_as_float(hp & 0xffff0000u);
                ah[i] = hp; al[i] = cvt_bf2(r1, r0);
            }
            __nv_bfloat16* ar = sA + srow * GSTRIDE + acb * 16;
            *reinterpret_cast<uint4*>(ar)      = make_uint4(ah[0],ah[1],ah[2],ah[3]);
            *reinterpret_cast<uint4*>(ar + 8)  = make_uint4(ah[4],ah[5],ah[6],ah[7]);
            *reinterpret_cast<uint4*>(ar + 32) = make_uint4(al[0],al[1],al[2],al[3]);
            *reinterpret_cast<uint4*>(ar + 40) = make_uint4(al[4],al[5],al[6],al[7]);
            *reinterpret_cast<uint4*>(ar + 64) = make_uint4(ah[0],ah[1],ah[2],ah[3]);
            *reinterpret_cast<uint4*>(ar + 72) = make_uint4(ah[4],ah[5],ah[6],ah[7]);
        }
        CP_WAIT(0);
        __syncthreads();

        if (kc + 1 < 6) {
            stageB(kc + 1, (kc + 1) & 1);
            CP_COMMIT();
            int k0 = (kc + 1) * 32 + acb * 16;
            #pragma unroll
            for (int q = 0; q < 4; q++) {
                float4 x = Arow ? *reinterpret_cast<const float4*>(Arow + k0 + q * 4)
                                : make_float4(0.f, 0.f, 0.f, 0.f);
                av[q*4+0]=x.x; av[q*4+1]=x.y; av[q*4+2]=x.z; av[q*4+3]=x.w;
            }
        }

        const uint32_t bBase = smem_u32(&sB[kc & 1][0]);
        #pragma unroll
        for (int s = 0; s < 6; s++) {
            uint32_t aA[2][4];
            #pragma unroll
            for (int mt = 0; mt < 2; mt++)
                ldsm_x4(aA[mt][0], aA[mt][1], aA[mt][2], aA[mt][3],
                        sAb + (uint32_t)(mw*32 + mt*16 + (t & 15)) * 208
                            + ((t >> 4) & 1) * 16 + s * 32);
            uint32_t bB[4][2];
            #pragma unroll
            for (int nt = 0; nt < 4; nt++)
                ldsm_x2(bB[nt][0], bB[nt][1],
                        bBase + (uint32_t)(nw*32 + nt*8 + (t & 7)) * 208
                              + ((t >> 3) & 1) * 16 + s * 32);
            #pragma unroll
            for (int mt = 0; mt < 2; mt++)
                #pragma unroll
                for (int nt = 0; nt < 4; nt++)
                    hmma_bf(C[mt][nt], aA[mt][0], aA[mt][1], aA[mt][2], aA[mt][3],
                            bB[nt][0], bB[nt][1]);
        }
        __syncthreads();
    }

    // ---- epilogue ----
    #pragma unroll
    for (int mt = 0; mt < 2; mt++) {
        #pragma unroll
        for (int cp = 0; cp < 2; cp++) {
            int row = m0 + mw * 32 + mt * 16 + (t >> 2) + cp * 8;
            if (MODE == 0 && row >= MROWS) continue;
            int b, n;
            if (MODE == 0) { b = (row >= NTOT) ? 1 : 0; n = row - b * NTOT; }
            #pragma unroll
            for (int nt = 0; nt < 4; nt++) {
                int o = n0 + nw * 32 + nt * 8 + (t & 3) * 2;
                float v0 = C[mt][nt][cp * 2];
                float v1 = C[mt][nt][cp * 2 + 1];
                if (MODE == 1) {
                    out[(size_t)row * CC + o]     = v0;
                    out[(size_t)row * CC + o + 1] = v1;
                } else {
                    if (o < CC) {
                        int hh = o / DD, d = o % DD;
                        float sc = T[hh] * LOG2E;
                        float a0 = v0 * sc, a1 = v1 * sc;
                        uint32_t hp = cvt_bf2(a1, a0);
                        float r0 = a0 - __uint_as_float(hp << 16);
                        float r1 = a1 - __uint_as_float(hp & 0xffff0000u);
                        uint32_t lp = cvt_bf2(r1, r0);
                        __nv_bfloat16* rw = g_Qp + ((size_t)(b * HH + hh) * NKP + n) * QK_COLS;
                        *reinterpret_cast<uint32_t*>(rw + d)      = hp;
                        *reinterpret_cast<uint32_t*>(rw + 24 + d) = lp;
                        *reinterpret_cast<uint32_t*>(rw + 48 + d) = hp;
                    } else if (o < 2 * CC) {
                        int oo = o - CC, hh = oo / DD, d = oo % DD;
                        uint32_t hp = cvt_bf2(v1, v0);
                        float r0 = v0 - __uint_as_float(hp << 16);
                        float r1 = v1 - __uint_as_float(hp & 0xffff0000u);
                        uint32_t lp = cvt_bf2(r1, r0);
                        __nv_bfloat16* rw = g_Kp + ((size_t)(b * HH + hh) * NKP + n) * QK_COLS;
                        *reinterpret_cast<uint32_t*>(rw + d)      = hp;
                        *reinterpret_cast<uint32_t*>(rw + 24 + d) = hp;
                        *reinterpret_cast<uint32_t*>(rw + 48 + d) = lp;
                    } else {
                        int oo = o - 2 * CC, hh = oo / DD, d = oo % DD;
                        __half2 h2 = __floats2half2_rn(v0, v1);
                        __half* rw = g_Vf + ((size_t)(b * HH + hh) * NKP + n) * V_COLS;
                        *reinterpret_cast<uint32_t*>(rw + d) = *reinterpret_cast<uint32_t*>(&h2);
                        if (d == 22)   // ones column for lsum-in-MMA
                            *reinterpret_cast<uint32_t*>(rw + 24) = 0x00003C00u;
                    }
                }
            }
        }
    }
}

// ---------------------------------------------------------------------------
// 2) Attention: R13/R15 mainloop shape, but 128-thread CTAs (128 queries,
//    4 warps, mt=2) so TWO CTAs co-reside per SM (regs ~252 -> 2x128x252
//    ~= 64.5K regs; smem 2x64KB <= 228KB). Barrier bubbles of one CTA are
//    covered by the other.
// smem: 2 stages x (K 128x176 = 22528 | V 128x80 = 10240) = 65536 B
// ---------------------------------------------------------------------------
#define STG2 32768
#define OV2  22528
#define ATT_SMEM 65536

__global__ __launch_bounds__(128, 2)
void attn_kernel() {
    extern __shared__ __align__(16) uint8_t dsm[];
    const uint32_t sb = smem_u32(dsm);

    const int tid = threadIdx.x;
    const int w   = tid >> 5;
    const int t   = tid & 31;
    const int bh  = blockIdx.z * HH + blockIdx.y;
    const int q0  = blockIdx.x * 128;

    // ---- K/V loader: thread tid owns row tid (10 K chunks + 5 V chunks) ----
    auto load_tile = [&](int j0, uint32_t kb) {
        const __nv_bfloat16* ks = g_Kp + ((size_t)bh * NKP + j0 + tid) * QK_COLS;
        uint32_t kdst = kb + tid * 176;
        #pragma unroll
        for (int u = 0; u < 10; u++) CP16(kdst + u * 16, ks + u * 8);
        const __half* vs = g_Vf + ((size_t)bh * NKP + j0 + tid) * V_COLS;
        uint32_t vdst = kb + OV2 + tid * 80;
        #pragma unroll
        for (int u = 0; u < 5; u++) CP16(vdst + u * 16, vs + u * 8);
    };
    load_tile(0, sb);
    CP_COMMIT();

    // ---- Q fragments direct from gmem (one-time) ----
    uint32_t aQ[2][5][4];
    {
        const uint8_t* qb = reinterpret_cast<const uint8_t*>(
            g_Qp + ((size_t)bh * NKP + q0 + w * 32 + (t >> 2)) * QK_COLS);
        #pragma unroll
        for (int mt = 0; mt < 2; mt++) {
            const uint8_t* qr = qb + mt * 16 * (QK_COLS * 2);
            #pragma unroll
            for (int s = 0; s < 5; s++) {
                const uint8_t* p = qr + s * 32 + (t & 3) * 4;
                aQ[mt][s][0] = *reinterpret_cast<const uint32_t*>(p);
                aQ[mt][s][1] = *reinterpret_cast<const uint32_t*>(p + 8 * (QK_COLS * 2));
                aQ[mt][s][2] = *reinterpret_cast<const uint32_t*>(p + 16);
                aQ[mt][s][3] = *reinterpret_cast<const uint32_t*>(p + 8 * (QK_COLS * 2) + 16);
            }
        }
    }

    float O[2][4][4];                     // nt=3 holds lsum in col 24
    float rowmax[2][2] = {{-1e30f, -1e30f}, {-1e30f, -1e30f}};
    #pragma unroll
    for (int mt = 0; mt < 2; mt++)
        #pragma unroll
        for (int nt = 0; nt < 4; nt++)
            #pragma unroll
            for (int c = 0; c < 4; c++) O[mt][nt][c] = 0.f;

    for (int kt = 0; kt < KTILES2; ++kt) {
        if (kt + 1 < KTILES2) {
            load_tile((kt + 1) * 128, sb + ((kt + 1) & 1) * STG2);
            CP_COMMIT();
            CP_WAIT(1);
        } else {
            CP_WAIT(0);
        }
        __syncthreads();

        const uint32_t kb = sb + (kt & 1) * STG2;
        const uint32_t krow_off = (uint32_t)(t & 7) * 176 + (((t >> 3) & 1) ? 16u : 0u);
        const uint32_t vrow_off = (uint32_t)(t & 15) * 80;

        #pragma unroll
        for (int half = 0; half < 2; half++) {
            const uint32_t kh_base = kb + (uint32_t)(half * 64) * 176;
            const uint32_t vh_base = kb + OV2 + (uint32_t)(half * 64) * 80;

            float C[2][8][4];
            #pragma unroll
            for (int mt = 0; mt < 2; mt++)
                #pragma unroll
                for (int nt = 0; nt < 8; nt++)
                    #pragma unroll
                    for (int c = 0; c < 4; c++) C[mt][nt][c] = 0.f;

            #pragma unroll
            for (int s = 0; s < 5; s++) {
                uint32_t b0[8], b1[8];
                #pragma unroll
                for (int nt = 0; nt < 8; nt++)
                    ldsm_x2(b0[nt], b1[nt],
                            kh_base + (uint32_t)nt * 8 * 176 + s * 32 + krow_off);
                #pragma unroll
                for (int nt = 0; nt < 8; nt++) {
                    hmma_bf(C[0][nt], aQ[0][s][0], aQ[0][s][1], aQ[0][s][2], aQ[0][s][3],
                            b0[nt], b1[nt]);
                    hmma_bf(C[1][nt], aQ[1][s][0], aQ[1][s][1], aQ[1][s][2], aQ[1][s][3],
                            b0[nt], b1[nt]);
                }
            }

            float tm[2][2];
            #pragma unroll
            for (int mt = 0; mt < 2; mt++) {
                float a = fmaxf(C[mt][0][0], C[mt][0][1]);
                float b = fmaxf(C[mt][0][2], C[mt][0][3]);
                #pragma unroll
                for (int nt = 1; nt < 8; nt++) {
                    a = fmaxf(a, fmaxf(C[mt][nt][0], C[mt][nt][1]));
                    b = fmaxf(b, fmaxf(C[mt][nt][2], C[mt][nt][3]));
                }
                tm[mt][0] = a; tm[mt][1] = b;
            }
            #pragma unroll
            for (int mt = 0; mt < 2; mt++)
                #pragma unroll
                for (int hf = 0; hf < 2; hf++) {
                    tm[mt][hf] = fmaxf(tm[mt][hf], __shfl_xor_sync(0xffffffffu, tm[mt][hf], 1));
                    tm[mt][hf] = fmaxf(tm[mt][hf], __shfl_xor_sync(0xffffffffu, tm[mt][hf], 2));
                }
            float M[2][2], f[2][2];
            #pragma unroll
            for (int mt = 0; mt < 2; mt++)
                #pragma unroll
                for (int hf = 0; hf < 2; hf++) {
                    M[mt][hf] = fmaxf(rowmax[mt][hf], tm[mt][hf]);
                    f[mt][hf] = ex2f(rowmax[mt][hf] - M[mt][hf]);
                    rowmax[mt][hf] = M[mt][hf];
                }
            #pragma unroll
            for (int mt = 0; mt < 2; mt++)
                #pragma unroll
                for (int nt = 0; nt < 4; nt++) {
                    O[mt][nt][0] *= f[mt][0]; O[mt][nt][1] *= f[mt][0];
                    O[mt][nt][2] *= f[mt][1]; O[mt][nt][3] *= f[mt][1];
                }

            uint32_t PH[2][4][4];
            #pragma unroll
            for (int mt = 0; mt < 2; mt++) {
                #pragma unroll
                for (int nt = 0; nt < 8; nt++) {
                    uint32_t x01 = cvt_f16x2(C[mt][nt][1] - M[mt][0], C[mt][nt][0] - M[mt][0]);
                    uint32_t x23 = cvt_f16x2(C[mt][nt][3] - M[mt][1], C[mt][nt][2] - M[mt][1]);
                    int ks = nt >> 1, hf2 = nt & 1;
                    PH[mt][ks][hf2 * 2 + 0] = ex2_f16x2(x01);
                    PH[mt][ks][hf2 * 2 + 1] = ex2_f16x2(x23);
                }
            }

            #pragma unroll
            for (int ks = 0; ks < 4; ks++) {
                #pragma unroll
                for (int nt = 0; nt < 4; nt++) {
                    uint32_t v0, v1;
                    ldsm_x2_t(v0, v1, vh_base + (uint32_t)(ks * 16) * 80 + nt * 16 + vrow_off);
                    hmma_f16(O[0][nt], PH[0][ks][0], PH[0][ks][1], PH[0][ks][2], PH[0][ks][3], v0, v1);
                    hmma_f16(O[1][nt], PH[1][ks][0], PH[1][ks][1], PH[1][ks][2], PH[1][ks][3], v0, v1);
                }
            }
        }
        __syncthreads();
    }

    // ---- lsum in O[mt][3] col 24; broadcast within quad ----
    float inv[2][2];
    #pragma unroll
    for (int mt = 0; mt < 2; mt++)
        #pragma unroll
        for (int hf = 0; hf < 2; hf++) {
            float v = __shfl_sync(0xffffffffu, O[mt][3][hf * 2], (t >> 2) << 2);
            inv[mt][hf] = 1.f / v;
        }

    // ---- epilogue: O / l -> g_O ----
    #pragma unroll
    for (int mt = 0; mt < 2; mt++) {
        #pragma unroll
        for (int c = 0; c < 4; c++) {
            int row = w * 32 + mt * 16 + (t >> 2) + ((c >> 1) ? 8 : 0);
            int q = q0 + row;
            if (q < NTOT) {
                float iv = inv[mt][c >> 1];
                #pragma unroll
                for (int nt = 0; nt < 3; nt++) {
                    int d = blockIdx.y * DD + nt * 8 + (t & 3) * 2 + (c & 1);
                    g_O[(size_t)(blockIdx.z * NTOT + q) * CC + d] = O[mt][nt][c] * iv;
                }
            }
        }
    }
}

// ---------------------------------------------------------------------------
// launch
// ---------------------------------------------------------------------------
extern "C" void kernel_launch(void* const* d_in, const int* in_sizes, int n_in,
                              void* d_out, int out_size) {
    const float* X  = nullptr;
    const float* S  = nullptr;
    const float* Wq = nullptr;
    const float* Wo = nullptr;
    const float* T  = nullptr;
    for (int i = 0; i < n_in; i++) {
        switch (in_sizes[i]) {
            case BB * NQ * CC:  X  = (const float*)d_in[i]; break;
            case BB * NS * CC:  S  = (const float*)d_in[i]; break;
            case 3 * CC * CC:   Wq = (const float*)d_in[i]; break;
            case CC * CC:       Wo = (const float*)d_in[i]; break;
            case HH:            T  = (const float*)d_in[i]; break;
        }
    }
    __nv_bfloat16* dBq = nullptr;
    __nv_bfloat16* dBo = nullptr;
    cudaGetSymbolAddress((void**)&dBq, g_Bq);
    cudaGetSymbolAddress((void**)&dBo, g_Bo);

    // 0) pack weights (tiny, one-time per launch)
    pack_b_kernel<<<(576 * 6 + 255) / 256, 256>>>(Wq, dBq, 576);
    pack_b_kernel<<<(192 * 6 + 255) / 256, 256>>>(Wo, dBo, 192);

    // 1) QKV projection
    {
        dim3 grid((MROWS + 63) / 64, (3 * CC) / 64);   // (129, 9)
        split_gemm_kernel<0><<<grid, 128>>>(X, S, dBq, T, nullptr);
    }
    // 2) attention (128 threads/CTA -> 2 CTAs per SM)
    {
        cudaFuncSetAttribute(attn_kernel, cudaFuncAttributeMaxDynamicSharedMemorySize, ATT_SMEM);
        dim3 grid(QTILES, HH, BB);                      // (33, 8, 2)
        attn_kernel<<<grid, 128, ATT_SMEM>>>();
    }
    // 3) output projection
    {
        dim3 grid((BB * NQ) / 64, CC / 64);             // (128, 3)
        split_gemm_kernel<1><<<grid, 128>>>(nullptr, nullptr, dBo, T, (float*)d_out);
    }
}

// round 17
// speedup vs baseline: 1.2329x; 1.2329x over previous
#include <cuda_runtime.h>
#include <cuda_bf16.h>
#include <cuda_fp16.h>
#include <cstdint>

// Problem constants
#define BB    2
#define NQ    4096
#define NS    8
#define NTOT  4104          // NQ + NS
#define CC    192
#define HH    8
#define DD    24            // CC / HH
#define MROWS (BB*NTOT)     // 8208
#define NKP   4352          // padded to 17*256
#define QTILES 17           // q-tiles of 256
#define KTILES2 33          // k-tiles of 128
#define LOG2E 1.4426950408889634f

// packed row widths (elements)
#define QK_COLS 88          // 80 data cols (5 ksteps x16) + 8 pad; 176B rows
#define V_COLS  40          // fp16: 24 data + ones col @24 + pad; 80B rows
#define PK_COLS 576         // packed B row: 6 chunks x 96

typedef unsigned long long u64;

// ---------------------------------------------------------------------------
// helpers
// ---------------------------------------------------------------------------
__device__ __forceinline__ float ex2f(float x) {
    float r; asm("ex2.approx.f32 %0, %1;" : "=f"(r) : "f"(x)); return r;
}
__device__ __forceinline__ uint32_t cvt_bf2(float hi, float lo) {
    uint32_t r; asm("cvt.rn.bf16x2.f32 %0, %1, %2;" : "=r"(r) : "f"(hi), "f"(lo)); return r;
}
__device__ __forceinline__ uint32_t cvt_f16x2(float hi, float lo) {
    uint32_t r; asm("cvt.rn.f16x2.f32 %0, %1, %2;" : "=r"(r) : "f"(hi), "f"(lo)); return r;
}
__device__ __forceinline__ uint32_t ex2_f16x2(uint32_t x) {
    uint32_t r; asm("ex2.approx.f16x2 %0, %1;" : "=r"(r) : "r"(x)); return r;
}
__device__ __forceinline__ void hmma_bf(float (&c)[4],
                                        uint32_t a0, uint32_t a1, uint32_t a2, uint32_t a3,
                                        uint32_t b0, uint32_t b1) {
    asm volatile(
        "mma.sync.aligned.m16n8k16.row.col.f32.bf16.bf16.f32 "
        "{%0,%1,%2,%3},{%4,%5,%6,%7},{%8,%9},{%0,%1,%2,%3};"
        : "+f"(c[0]), "+f"(c[1]), "+f"(c[2]), "+f"(c[3])
        : "r"(a0), "r"(a1), "r"(a2), "r"(a3), "r"(b0), "r"(b1));
}
__device__ __forceinline__ void hmma_f16(float (&c)[4],
                                         uint32_t a0, uint32_t a1, uint32_t a2, uint32_t a3,
                                         uint32_t b0, uint32_t b1) {
    asm volatile(
        "mma.sync.aligned.m16n8k16.row.col.f32.f16.f16.f32 "
        "{%0,%1,%2,%3},{%4,%5,%6,%7},{%8,%9},{%0,%1,%2,%3};"
        : "+f"(c[0]), "+f"(c[1]), "+f"(c[2]), "+f"(c[3])
        : "r"(a0), "r"(a1), "r"(a2), "r"(a3), "r"(b0), "r"(b1));
}
__device__ __forceinline__ uint32_t smem_u32(const void* p) {
    uint32_t a;
    asm("{ .reg .u64 t; cvta.to.shared.u64 t, %1; cvt.u32.u64 %0, t; }" : "=r"(a) : "l"(p));
    return a;
}
__device__ __forceinline__ void ldsm_x2(uint32_t& r0, uint32_t& r1, uint32_t addr) {
    asm volatile("ldmatrix.sync.aligned.m8n8.x2.shared.b16 {%0,%1}, [%2];"
                 : "=r"(r0), "=r"(r1) : "r"(addr));
}
__device__ __forceinline__ void ldsm_x4(uint32_t& r0, uint32_t& r1, uint32_t& r2, uint32_t& r3,
                                        uint32_t addr) {
    asm volatile("ldmatrix.sync.aligned.m8n8.x4.shared.b16 {%0,%1,%2,%3}, [%4];"
                 : "=r"(r0), "=r"(r1), "=r"(r2), "=r"(r3) : "r"(addr));
}
__device__ __forceinline__ void ldsm_x2_t(uint32_t& r0, uint32_t& r1, uint32_t addr) {
    asm volatile("ldmatrix.sync.aligned.m8n8.x2.trans.shared.b16 {%0,%1}, [%2];"
                 : "=r"(r0), "=r"(r1) : "r"(addr));
}
#define CP16(dst, src) \
    asm volatile("cp.async.cg.shared.global [%0], [%1], 16;" :: "r"(dst), "l"(src))
#define CP_COMMIT() asm volatile("cp.async.commit_group;" ::: "memory")
#define CP_WAIT(n)  asm volatile("cp.async.wait_group %0;" :: "n"(n) : "memory")

// ---------------------------------------------------------------------------
// Scratch (device globals; zero-initialized -> pad rows/cols stay 0)
// ---------------------------------------------------------------------------
__device__ __align__(16) __nv_bfloat16 g_Qp[16*NKP*QK_COLS];
__device__ __align__(16) __nv_bfloat16 g_Kp[16*NKP*QK_COLS];
__device__ __align__(16) __half        g_Vf[16*NKP*V_COLS];
__device__ __align__(16) float g_O[BB*NTOT*CC];
__device__ __align__(16) __nv_bfloat16 g_Bq[576*PK_COLS];
__device__ __align__(16) __nv_bfloat16 g_Bo[192*PK_COLS];

// ---------------------------------------------------------------------------
// 0) Pack B (one-time)
// ---------------------------------------------------------------------------
__global__ void pack_b_kernel(const float* __restrict__ W, __nv_bfloat16* __restrict__ dst,
                              int rows) {
    int idx = blockIdx.x * 256 + threadIdx.x;
    if (idx >= rows * 6) return;
    int row = idx / 6, ch = idx % 6;
    const float* src = W + (size_t)row * CC + ch * 32;
    uint32_t h[16], l[16];
    #pragma unroll
    for (int q = 0; q < 8; q++) {
        float4 x = *reinterpret_cast<const float4*>(src + q * 4);
        uint32_t h0 = cvt_bf2(x.y, x.x);
        float r0 = x.x - __uint_as_float(h0 << 16);
        float r1 = x.y - __uint_as_float(h0 & 0xffff0000u);
        uint32_t h1 = cvt_bf2(x.w, x.z);
        float r2 = x.z - __uint_as_float(h1 << 16);
        float r3 = x.w - __uint_as_float(h1 & 0xffff0000u);
        h[q*2]   = h0; l[q*2]   = cvt_bf2(r1, r0);
        h[q*2+1] = h1; l[q*2+1] = cvt_bf2(r3, r2);
    }
    uint4* d = reinterpret_cast<uint4*>(dst + (size_t)row * PK_COLS + ch * 96);
    #pragma unroll
    for (int i = 0; i < 4; i++) d[i]     = make_uint4(h[i*4], h[i*4+1], h[i*4+2], h[i*4+3]);
    #pragma unroll
    for (int i = 0; i < 4; i++) d[4 + i] = make_uint4(h[i*4], h[i*4+1], h[i*4+2], h[i*4+3]);
    #pragma unroll
    for (int i = 0; i < 4; i++) d[8 + i] = make_uint4(l[i*4], l[i*4+1], l[i*4+2], l[i*4+3]);
}

// ---------------------------------------------------------------------------
// 1&3) Split GEMM (R15): A fp32 + in-kernel split, B pre-packed + cp.async.
// ---------------------------------------------------------------------------
#define GSTRIDE 104

template<int MODE>
__global__ __launch_bounds__(128)
void split_gemm_kernel(const float* __restrict__ X,
                       const float* __restrict__ S,
                       const __nv_bfloat16* __restrict__ Bp,
                       const float* __restrict__ T,
                       float* __restrict__ out) {
    __shared__ __align__(16) __nv_bfloat16 sA[64 * GSTRIDE];
    __shared__ __align__(16) __nv_bfloat16 sB[2][64 * GSTRIDE];

    const int tid = threadIdx.x;
    const int w   = tid >> 5;
    const int t   = tid & 31;
    const int mw  = w >> 1;
    const int nw  = w & 1;
    const int m0  = blockIdx.x * 64;
    const int n0  = blockIdx.y * 64;

    const int srow = tid >> 1;
    const int half = tid & 1;

    const float* Arow = nullptr;
    if (MODE == 0) {
        int gr = m0 + srow;
        if (gr < MROWS) {
            int b = (gr >= NTOT) ? 1 : 0;
            int n = gr - b * NTOT;
            if (n < NQ) Arow = X + (size_t)(b * NQ + n) * CC;
            else        Arow = S + (size_t)(b * NS + (n - NQ)) * CC;
        }
    } else {
        int gr = m0 + srow;
        int b = gr >> 12;
        int n = gr & 4095;
        Arow = g_O + (size_t)(b * NTOT + n) * CC;
    }
    const __nv_bfloat16* Brow = Bp + (size_t)(n0 + srow) * PK_COLS;

    auto stageB = [&](int ch, int buf) {
        const __nv_bfloat16* bs = Brow + ch * 96 + half * 48;
        uint32_t bd = smem_u32(&sB[buf][0]) + srow * 208 + half * 96;
        #pragma unroll
        for (int u = 0; u < 6; u++) CP16(bd + u * 16, bs + u * 8);
    };

    stageB(0, 0);
    CP_COMMIT();

    float av[16];
    const int acb = half;
    {
        #pragma unroll
        for (int q = 0; q < 4; q++) {
            float4 x = Arow ? *reinterpret_cast<const float4*>(Arow + acb * 16 + q * 4)
                            : make_float4(0.f, 0.f, 0.f, 0.f);
            av[q*4+0]=x.x; av[q*4+1]=x.y; av[q*4+2]=x.z; av[q*4+3]=x.w;
        }
    }

    float C[2][4][4];
    #pragma unroll
    for (int mt = 0; mt < 2; mt++)
        #pragma unroll
        for (int nt = 0; nt < 4; nt++)
            #pragma unroll
            for (int c = 0; c < 4; c++) C[mt][nt][c] = 0.f;

    const uint32_t sAb = smem_u32(sA);

    for (int kc = 0; kc < 6; kc++) {
        {
            uint32_t ah[8], al[8];
            #pragma unroll
            for (int i = 0; i < 8; i++) {
                float a0 = av[2*i], a1 = av[2*i+1];
                uint32_t hp = cvt_bf2(a1, a0);
                float r0 = a0 - __uint_as_float(hp << 16);
                float r1 = a1 - __uint_as_float(hp & 0xffff0000u);
                ah[i] = hp; al[i] = cvt_bf2(r1, r0);
            }
            __nv_bfloat16* ar = sA + srow * GSTRIDE + acb * 16;
            *reinterpret_cast<uint4*>(ar)      = make_uint4(ah[0],ah[1],ah[2],ah[3]);
            *reinterpret_cast<uint4*>(ar + 8)  = make_uint4(ah[4],ah[5],ah[6],ah[7]);
            *reinterpret_cast<uint4*>(ar + 32) = make_uint4(al[0],al[1],al[2],al[3]);
            *reinterpret_cast<uint4*>(ar + 40) = make_uint4(al[4],al[5],al[6],al[7]);
            *reinterpret_cast<uint4*>(ar + 64) = make_uint4(ah[0],ah[1],ah[2],ah[3]);
            *reinterpret_cast<uint4*>(ar + 72) = make_uint4(ah[4],ah[5],ah[6],ah[7]);
        }
        CP_WAIT(0);
        __syncthreads();

        if (kc + 1 < 6) {
            stageB(kc + 1, (kc + 1) & 1);
            CP_COMMIT();
            int k0 = (kc + 1) * 32 + acb * 16;
            #pragma unroll
            for (int q = 0; q < 4; q++) {
                float4 x = Arow ? *reinterpret_cast<const float4*>(Arow + k0 + q * 4)
                                : make_float4(0.f, 0.f, 0.f, 0.f);
                av[q*4+0]=x.x; av[q*4+1]=x.y; av[q*4+2]=x.z; av[q*4+3]=x.w;
            }
        }

        const uint32_t bBase = smem_u32(&sB[kc & 1][0]);
        #pragma unroll
        for (int s = 0; s < 6; s++) {
            uint32_t aA[2][4];
            #pragma unroll
            for (int mt = 0; mt < 2; mt++)
                ldsm_x4(aA[mt][0], aA[mt][1], aA[mt][2], aA[mt][3],
                        sAb + (uint32_t)(mw*32 + mt*16 + (t & 15)) * 208
                            + ((t >> 4) & 1) * 16 + s * 32);
            uint32_t bB[4][2];
            #pragma unroll
            for (int nt = 0; nt < 4; nt++)
                ldsm_x2(bB[nt][0], bB[nt][1],
                        bBase + (uint32_t)(nw*32 + nt*8 + (t & 7)) * 208
                              + ((t >> 3) & 1) * 16 + s * 32);
            #pragma unroll
            for (int mt = 0; mt < 2; mt++)
                #pragma unroll
                for (int nt = 0; nt < 4; nt++)
                    hmma_bf(C[mt][nt], aA[mt][0], aA[mt][1], aA[mt][2], aA[mt][3],
                            bB[nt][0], bB[nt][1]);
        }
        __syncthreads();
    }

    #pragma unroll
    for (int mt = 0; mt < 2; mt++) {
        #pragma unroll
        for (int cp = 0; cp < 2; cp++) {
            int row = m0 + mw * 32 + mt * 16 + (t >> 2) + cp * 8;
            if (MODE == 0 && row >= MROWS) continue;
            int b, n;
            if (MODE == 0) { b = (row >= NTOT) ? 1 : 0; n = row - b * NTOT; }
            #pragma unroll
            for (int nt = 0; nt < 4; nt++) {
                int o = n0 + nw * 32 + nt * 8 + (t & 3) * 2;
                float v0 = C[mt][nt][cp * 2];
                float v1 = C[mt][nt][cp * 2 + 1];
                if (MODE == 1) {
                    out[(size_t)row * CC + o]     = v0;
                    out[(size_t)row * CC + o + 1] = v1;
                } else {
                    if (o < CC) {
                        int hh = o / DD, d = o % DD;
                        float sc = T[hh] * LOG2E;
                        float a0 = v0 * sc, a1 = v1 * sc;
                        uint32_t hp = cvt_bf2(a1, a0);
                        float r0 = a0 - __uint_as_float(hp << 16);
                        float r1 = a1 - __uint_as_float(hp & 0xffff0000u);
                        uint32_t lp = cvt_bf2(r1, r0);
                        __nv_bfloat16* rw = g_Qp + ((size_t)(b * HH + hh) * NKP + n) * QK_COLS;
                        *reinterpret_cast<uint32_t*>(rw + d)      = hp;
                        *reinterpret_cast<uint32_t*>(rw + 24 + d) = lp;
                        *reinterpret_cast<uint32_t*>(rw + 48 + d) = hp;
                    } else if (o < 2 * CC) {
                        int oo = o - CC, hh = oo / DD, d = oo % DD;
                        uint32_t hp = cvt_bf2(v1, v0);
                        float r0 = v0 - __uint_as_float(hp << 16);
                        float r1 = v1 - __uint_as_float(hp & 0xffff0000u);
                        uint32_t lp = cvt_bf2(r1, r0);
                        __nv_bfloat16* rw = g_Kp + ((size_t)(b * HH + hh) * NKP + n) * QK_COLS;
                        *reinterpret_cast<uint32_t*>(rw + d)      = hp;
                        *reinterpret_cast<uint32_t*>(rw + 24 + d) = hp;
                        *reinterpret_cast<uint32_t*>(rw + 48 + d) = lp;
                    } else {
                        int oo = o - 2 * CC, hh = oo / DD, d = oo % DD;
                        __half2 h2 = __floats2half2_rn(v0, v1);
                        __half* rw = g_Vf + ((size_t)(b * HH + hh) * NKP + n) * V_COLS;
                        *reinterpret_cast<uint32_t*>(rw + d) = *reinterpret_cast<uint32_t*>(&h2);
                        if (d == 22)
                            *reinterpret_cast<uint32_t*>(rw + 24) = 0x00003C00u;
                    }
                }
            }
        }
    }
}

// ---------------------------------------------------------------------------
// 2) Attention: R13 shape (256 thr, 256 q, TK=128), half-pipelined tile:
//    S0 -> SM0 -> S1 -> PV0 -> SM1 -> PV1 (softmax latency hidden under MMAs).
// smem: 2 stages x (K 128x176 = 22528 | V 128x80 = 10240) = 65536 B
// ---------------------------------------------------------------------------
#define STG2 32768
#define OV2  22528
#define ATT_SMEM 65536

__global__ __launch_bounds__(256, 1)
void attn_kernel() {
    extern __shared__ __align__(16) uint8_t dsm[];
    const uint32_t sb = smem_u32(dsm);

    const int tid = threadIdx.x;
    const int w   = tid >> 5;
    const int t   = tid & 31;
    const int bh  = blockIdx.z * HH + blockIdx.y;
    const int q0  = blockIdx.x * 256;

    const int krow = tid >> 1;
    const int kgb  = (tid & 1) * 5;
    auto load_tile = [&](int j0, uint32_t kb) {
        const __nv_bfloat16* ks = g_Kp + ((size_t)bh * NKP + j0 + krow) * QK_COLS;
        uint32_t kdst = kb + krow * 176;
        #pragma unroll
        for (int u = 0; u < 5; u++) CP16(kdst + (kgb + u) * 16, ks + (kgb + u) * 8);
        #pragma unroll
        for (int i = 0; i < 3; i++) {
            int c = tid + 256 * i;
            if (c < 640) {
                int vr = c / 5, vc = c % 5;
                CP16(kb + OV2 + vr * 80 + vc * 16,
                     g_Vf + ((size_t)bh * NKP + j0 + vr) * V_COLS + vc * 8);
            }
        }
    };
    load_tile(0, sb);
    CP_COMMIT();

    uint32_t aQ[2][5][4];
    {
        const uint8_t* qb = reinterpret_cast<const uint8_t*>(
            g_Qp + ((size_t)bh * NKP + q0 + w * 32 + (t >> 2)) * QK_COLS);
        #pragma unroll
        for (int mt = 0; mt < 2; mt++) {
            const uint8_t* qr = qb + mt * 16 * (QK_COLS * 2);
            #pragma unroll
            for (int s = 0; s < 5; s++) {
                const uint8_t* p = qr + s * 32 + (t & 3) * 4;
                aQ[mt][s][0] = *reinterpret_cast<const uint32_t*>(p);
                aQ[mt][s][1] = *reinterpret_cast<const uint32_t*>(p + 8 * (QK_COLS * 2));
                aQ[mt][s][2] = *reinterpret_cast<const uint32_t*>(p + 16);
                aQ[mt][s][3] = *reinterpret_cast<const uint32_t*>(p + 8 * (QK_COLS * 2) + 16);
            }
        }
    }

    float O[2][4][4];                     // nt=3 holds lsum in col 24
    float rowmax[2][2] = {{-1e30f, -1e30f}, {-1e30f, -1e30f}};
    #pragma unroll
    for (int mt = 0; mt < 2; mt++)
        #pragma unroll
        for (int nt = 0; nt < 4; nt++)
            #pragma unroll
            for (int c = 0; c < 4; c++) O[mt][nt][c] = 0.f;

    const uint32_t krow_off = (uint32_t)(t & 7) * 176 + (((t >> 3) & 1) ? 16u : 0u);
    const uint32_t vrow_off = (uint32_t)(t & 15) * 80;

    float C[2][8][4];

    // ---- phase lambdas (inlined; pipeline order set at call sites) ----
    auto s_mma = [&](uint32_t kh_base) {
        #pragma unroll
        for (int mt = 0; mt < 2; mt++)
            #pragma unroll
            for (int nt = 0; nt < 8; nt++)
                #pragma unroll
                for (int c = 0; c < 4; c++) C[mt][nt][c] = 0.f;
        #pragma unroll
        for (int s = 0; s < 5; s++) {
            uint32_t b0[8], b1[8];
            #pragma unroll
            for (int nt = 0; nt < 8; nt++)
                ldsm_x2(b0[nt], b1[nt],
                        kh_base + (uint32_t)nt * 8 * 176 + s * 32 + krow_off);
            #pragma unroll
            for (int nt = 0; nt < 8; nt++) {
                hmma_bf(C[0][nt], aQ[0][s][0], aQ[0][s][1], aQ[0][s][2], aQ[0][s][3],
                        b0[nt], b1[nt]);
                hmma_bf(C[1][nt], aQ[1][s][0], aQ[1][s][1], aQ[1][s][2], aQ[1][s][3],
                        b0[nt], b1[nt]);
            }
        }
    };

    auto softmax = [&](uint32_t (&PH)[2][4][4]) {
        float tm[2][2];
        #pragma unroll
        for (int mt = 0; mt < 2; mt++) {
            float a = fmaxf(C[mt][0][0], C[mt][0][1]);
            float b = fmaxf(C[mt][0][2], C[mt][0][3]);
            #pragma unroll
            for (int nt = 1; nt < 8; nt++) {
                a = fmaxf(a, fmaxf(C[mt][nt][0], C[mt][nt][1]));
                b = fmaxf(b, fmaxf(C[mt][nt][2], C[mt][nt][3]));
            }
            tm[mt][0] = a; tm[mt][1] = b;
        }
        #pragma unroll
        for (int mt = 0; mt < 2; mt++)
            #pragma unroll
            for (int hf = 0; hf < 2; hf++) {
                tm[mt][hf] = fmaxf(tm[mt][hf], __shfl_xor_sync(0xffffffffu, tm[mt][hf], 1));
                tm[mt][hf] = fmaxf(tm[mt][hf], __shfl_xor_sync(0xffffffffu, tm[mt][hf], 2));
            }
        float M[2][2], f[2][2];
        #pragma unroll
        for (int mt = 0; mt < 2; mt++)
            #pragma unroll
            for (int hf = 0; hf < 2; hf++) {
                M[mt][hf] = fmaxf(rowmax[mt][hf], tm[mt][hf]);
                f[mt][hf] = ex2f(rowmax[mt][hf] - M[mt][hf]);
                rowmax[mt][hf] = M[mt][hf];
            }
        #pragma unroll
        for (int mt = 0; mt < 2; mt++)
            #pragma unroll
            for (int nt = 0; nt < 4; nt++) {
                O[mt][nt][0] *= f[mt][0]; O[mt][nt][1] *= f[mt][0];
                O[mt][nt][2] *= f[mt][1]; O[mt][nt][3] *= f[mt][1];
            }
        #pragma unroll
        for (int mt = 0; mt < 2; mt++) {
            #pragma unroll
            for (int nt = 0; nt < 8; nt++) {
                uint32_t x01 = cvt_f16x2(C[mt][nt][1] - M[mt][0], C[mt][nt][0] - M[mt][0]);
                uint32_t x23 = cvt_f16x2(C[mt][nt][3] - M[mt][1], C[mt][nt][2] - M[mt][1]);
                int ks = nt >> 1, hf2 = nt & 1;
                PH[mt][ks][hf2 * 2 + 0] = ex2_f16x2(x01);
                PH[mt][ks][hf2 * 2 + 1] = ex2_f16x2(x23);
            }
        }
    };

    auto pv = [&](uint32_t vh_base, uint32_t (&PH)[2][4][4]) {
        #pragma unroll
        for (int ks = 0; ks < 4; ks++) {
            #pragma unroll
            for (int nt = 0; nt < 4; nt++) {
                uint32_t v0, v1;
                ldsm_x2_t(v0, v1, vh_base + (uint32_t)(ks * 16) * 80 + nt * 16 + vrow_off);
                hmma_f16(O[0][nt], PH[0][ks][0], PH[0][ks][1], PH[0][ks][2], PH[0][ks][3], v0, v1);
                hmma_f16(O[1][nt], PH[1][ks][0], PH[1][ks][1], PH[1][ks][2], PH[1][ks][3], v0, v1);
            }
        }
    };

    for (int kt = 0; kt < KTILES2; ++kt) {
        if (kt + 1 < KTILES2) {
            load_tile((kt + 1) * 128, sb + ((kt + 1) & 1) * STG2);
            CP_COMMIT();
            CP_WAIT(1);
        } else {
            CP_WAIT(0);
        }
        __syncthreads();

        const uint32_t kb = sb + (kt & 1) * STG2;
        const uint32_t kh0 = kb;
        const uint32_t kh1 = kb + (uint32_t)64 * 176;
        const uint32_t vh0 = kb + OV2;
        const uint32_t vh1 = kb + OV2 + (uint32_t)64 * 80;

        uint32_t PHa[2][4][4], PHb[2][4][4];
        // software pipeline: S0 | SM0 | S1 overlaps SM0 latency | PV0 | SM1 | PV1
        s_mma(kh0);
        softmax(PHa);
        s_mma(kh1);          // hides SM0's MUFU/shfl chain + gives PV0 slack
        pv(vh0, PHa);
        softmax(PHb);
        pv(vh1, PHb);

        __syncthreads();
    }

    // ---- lsum in O[mt][3] col 24; broadcast within quad ----
    float inv[2][2];
    #pragma unroll
    for (int mt = 0; mt < 2; mt++)
        #pragma unroll
        for (int hf = 0; hf < 2; hf++) {
            float v = __shfl_sync(0xffffffffu, O[mt][3][hf * 2], (t >> 2) << 2);
            inv[mt][hf] = 1.f / v;
        }

    // ---- epilogue: O / l -> g_O ----
    #pragma unroll
    for (int mt = 0; mt < 2; mt++) {
        #pragma unroll
        for (int c = 0; c < 4; c++) {
            int row = w * 32 + mt * 16 + (t >> 2) + ((c >> 1) ? 8 : 0);
            int q = q0 + row;
            if (q < NTOT) {
                float iv = inv[mt][c >> 1];
                #pragma unroll
                for (int nt = 0; nt < 3; nt++) {
                    int d = blockIdx.y * DD + nt * 8 + (t & 3) * 2 + (c & 1);
                    g_O[(size_t)(blockIdx.z * NTOT + q) * CC + d] = O[mt][nt][c] * iv;
                }
            }
        }
    }
}

// ---------------------------------------------------------------------------
// launch
// ---------------------------------------------------------------------------
extern "C" void kernel_launch(void* const* d_in, const int* in_sizes, int n_in,
                              void* d_out, int out_size) {
    const float* X  = nullptr;
    const float* S  = nullptr;
    const float* Wq = nullptr;
    const float* Wo = nullptr;
    const float* T  = nullptr;
    for (int i = 0; i < n_in; i++) {
        switch (in_sizes[i]) {
            case BB * NQ * CC:  X  = (const float*)d_in[i]; break;
            case BB * NS * CC:  S  = (const float*)d_in[i]; break;
            case 3 * CC * CC:   Wq = (const float*)d_in[i]; break;
            case CC * CC:       Wo = (const float*)d_in[i]; break;
            case HH:            T  = (const float*)d_in[i]; break;
        }
    }
    __nv_bfloat16* dBq = nullptr;
    __nv_bfloat16* dBo = nullptr;
    cudaGetSymbolAddress((void**)&dBq, g_Bq);
    cudaGetSymbolAddress((void**)&dBo, g_Bo);

    // 0) pack weights (tiny, one-time per launch)
    pack_b_kernel<<<(576 * 6 + 255) / 256, 256>>>(Wq, dBq, 576);
    pack_b_kernel<<<(192 * 6 + 255) / 256, 256>>>(Wo, dBo, 192);

    // 1) QKV projection
    {
        dim3 grid((MROWS + 63) / 64, (3 * CC) / 64);   // (129, 9)
        split_gemm_kernel<0><<<grid, 128>>>(X, S, dBq, T, nullptr);
    }
    // 2) attention (256 threads, half-pipelined tiles)
    {
        cudaFuncSetAttribute(attn_kernel, cudaFuncAttributeMaxDynamicSharedMemorySize, ATT_SMEM);
        dim3 grid(QTILES, HH, BB);                      // (17, 8, 2)
        attn_kernel<<<grid, 256, ATT_SMEM>>>();
    }
    // 3) output projection
    {
        dim3 grid((BB * NQ) / 64, CC / 64);             // (128, 3)
        split_gemm_kernel<1><<<grid, 128>>>(nullptr, nullptr, dBo, T, (float*)d_out);
    }
}